// round 16
// baseline (speedup 1.0000x reference)
#include <cuda_runtime.h>
#include <cuda_bf16.h>
#include <math.h>
#include <stdint.h>

// Problem constants: T=8192 tokens, E=8 experts, H=2048, I=5632, top_k=2
#define T_TOK   8192
#define NE      8
#define H_DIM   2048
#define I_DIM   5632
#define TOPK    2

#define ALIGN_M   128
#define PAIR_CAP  (T_TOK * TOPK + NE * ALIGN_M)   // 17408
#define NTILES_M  (PAIR_CAP / ALIGN_M)            // 136

// interleaved hi/lo row lengths in u32: 16 u32 per 16-k chunk (8 hi + 8 lo)
#define HROW 2048
#define IROW 5632

#define KBLK       32                  // k per stage = two 16-k chunks
#define STAGES     3
#define STAGE_U32  8192                // 32 KB per stage (both passes)
#define SMEM_SZ    (STAGES * STAGE_U32 * 4)   // 98304 B

// ---------------- device global scratch (allocation-free) ----------------
__device__ int   g_off[NE];
__device__ int   g_cur[NE];
__device__ int   g_tok_id[T_TOK * TOPK];
__device__ float g_tok_w [T_TOK * TOPK];
__device__ int   g_pair_token [PAIR_CAP];
__device__ float g_pair_w     [PAIR_CAP];
__device__ int   g_pair_expert[PAIR_CAP];

// interleaved bf16 hi/lo operands: per 16-k chunk (16 u32), 4 uint4 groups:
// group t = {hi(kp t), hi(kp t+4), lo(kp t), lo(kp t+4)}, t = 0..3
__device__ uint32_t g_hid[(size_t)T_TOK * HROW];
__device__ uint32_t g_w1 [(size_t)NE * I_DIM * HROW];
__device__ uint32_t g_w3 [(size_t)NE * I_DIM * HROW];
__device__ uint32_t g_w2g[(size_t)NE * H_DIM * IROW];
__device__ uint32_t g_act[(size_t)PAIR_CAP * IROW];

// ---------------- helpers ----------------
__device__ __forceinline__ uint32_t smem_u32(const void* p) {
    uint32_t a;
    asm("{ .reg .u64 t; cvta.to.shared.u64 t, %1; cvt.u32.u64 %0, t; }" : "=r"(a) : "l"(p));
    return a;
}
__device__ __forceinline__ void cp16(uint32_t dst, const void* src, uint32_t src_sz) {
    asm volatile("cp.async.cg.shared.global [%0], [%1], 16, %2;"
                 :: "r"(dst), "l"(src), "r"(src_sz) : "memory");
}
#define CP_COMMIT() asm volatile("cp.async.commit_group;" ::: "memory")
#define CP_WAIT1()  asm volatile("cp.async.wait_group 1;"  ::: "memory")

// m16n8k16 bf16 mma, fp32 accumulate
__device__ __forceinline__ void mma_bf16(float* c, uint32_t a0, uint32_t a1,
                                         uint32_t a2, uint32_t a3,
                                         uint32_t b0, uint32_t b1) {
    asm volatile(
        "mma.sync.aligned.m16n8k16.row.col.f32.bf16.bf16.f32 "
        "{%0,%1,%2,%3}, {%4,%5,%6,%7}, {%8,%9}, {%0,%1,%2,%3};"
        : "+f"(c[0]), "+f"(c[1]), "+f"(c[2]), "+f"(c[3])
        : "r"(a0), "r"(a1), "r"(a2), "r"(a3), "r"(b0), "r"(b1));
}

__device__ __forceinline__ float silu_mul(float g, float u, float wt) {
    return wt * u * (g / (1.0f + __expf(-g)));
}
__device__ __forceinline__ uint32_t pack2(__nv_bfloat16 a, __nv_bfloat16 b) {
    return (uint32_t)__bfloat16_as_ushort(a) | ((uint32_t)__bfloat16_as_ushort(b) << 16);
}

// ---------------- fused conversion for hidden+w1+w3 (H-length rows) ----------------
__global__ void conv_all(const float* __restrict__ hid,
                         const float* __restrict__ w1,
                         const float* __restrict__ w3) {
    size_t idx = (size_t)blockIdx.x * 256 + threadIdx.x;
    int row = (int)(idx >> 10);
    int p   = (int)(idx & 1023);
    int m = p & 7, chunk = p >> 3;
    int kp = ((m & 1) << 2) | (m >> 1);

    const float* src; uint32_t* dst; int r2;
    if (row < T_TOK)                    { src = hid; dst = g_hid; r2 = row; }
    else if (row < T_TOK + NE * I_DIM)  { src = w1;  dst = g_w1;  r2 = row - T_TOK; }
    else                                { src = w3;  dst = g_w3;  r2 = row - T_TOK - NE * I_DIM; }

    const float* s = src + ((size_t)r2 << 11) + chunk * 16 + kp * 2;
    float v0 = s[0], v1 = s[1];
    __nv_bfloat16 h0 = __float2bfloat16(v0), h1 = __float2bfloat16(v1);
    __nv_bfloat16 l0 = __float2bfloat16(v0 - __bfloat162float(h0));
    __nv_bfloat16 l1 = __float2bfloat16(v1 - __bfloat162float(h1));
    size_t o = ((size_t)r2 * HROW) + chunk * 16 + (m >> 1) * 4 + (m & 1);
    dst[o]     = pack2(h0, h1);
    dst[o + 2] = pack2(l0, l1);
}

// w2 conversion (I-length rows)
__global__ void conv_w2(const float* __restrict__ src) {
    int row = blockIdx.y;
    int p = blockIdx.x * 256 + threadIdx.x;   // 0..2815
    int m = p & 7, chunk = p >> 3;
    int kp = ((m & 1) << 2) | (m >> 1);
    const float* s = src + (size_t)row * I_DIM + chunk * 16 + kp * 2;
    float v0 = s[0], v1 = s[1];
    __nv_bfloat16 h0 = __float2bfloat16(v0), h1 = __float2bfloat16(v1);
    __nv_bfloat16 l0 = __float2bfloat16(v0 - __bfloat162float(h0));
    __nv_bfloat16 l1 = __float2bfloat16(v1 - __bfloat162float(h1));
    size_t o = (size_t)row * IROW + chunk * 16 + (m >> 1) * 4 + (m & 1);
    g_w2g[o]     = pack2(h0, h1);
    g_w2g[o + 2] = pack2(l0, l1);
}

// ---------------- routing: init + top-2 route ----------------
__global__ void init_route(const float* __restrict__ logits) {
    int idx = blockIdx.x * 256 + threadIdx.x;
    if (idx < PAIR_CAP) { g_pair_token[idx] = -1; g_pair_w[idx] = 0.0f; g_pair_expert[idx] = 0; }
    if (idx < T_TOK) {
        const float* lp = logits + (size_t)idx * NE;
        float best = -1e30f, second = -1e30f;
        int bi = -1, si = -1;
#pragma unroll
        for (int e = 0; e < NE; ++e) {
            float v = lp[e];
            if (v > best)        { second = best; si = bi; best = v; bi = e; }
            else if (v > second) { second = v; si = e; }
        }
        float e2 = expf(second - best);
        float denom = 1.0f + e2;
        g_tok_id[idx*2+0] = bi;  g_tok_w[idx*2+0] = 1.0f / denom;
        g_tok_id[idx*2+1] = si;  g_tok_w[idx*2+1] = e2 / denom;
    }
}

__global__ void scan_fill() {
    __shared__ int cnt[NE];
    const int tid = threadIdx.x;
    if (tid < NE) cnt[tid] = 0;
    __syncthreads();
    for (int t = tid; t < T_TOK; t += 1024) {
        atomicAdd(&cnt[g_tok_id[2*t]], 1);
        atomicAdd(&cnt[g_tok_id[2*t+1]], 1);
    }
    __syncthreads();
    if (tid == 0) {
        int off = 0;
        for (int e = 0; e < NE; ++e) {
            g_off[e] = off; g_cur[e] = off;
            off += ((cnt[e] + ALIGN_M - 1) / ALIGN_M) * ALIGN_M;
        }
    }
    __syncthreads();
    for (int t = tid; t < T_TOK; t += 1024) {
#pragma unroll
        for (int s = 0; s < TOPK; ++s) {
            int e = g_tok_id[t*2+s];
            int pos = atomicAdd(&g_cur[e], 1);
            g_pair_token[pos]  = t;
            g_pair_w[pos]      = g_tok_w[t*2+s];
            g_pair_expert[pos] = e;
        }
    }
}

__global__ void zero_out(float4* __restrict__ p) {
    int i = blockIdx.x * 256 + threadIdx.x;
    p[i] = make_float4(0.f, 0.f, 0.f, 0.f);
}

// =====================================================================
// pass 1: act = route_w * silu(X@w1^T) * (X@w3^T)   [bf16x3, interleaved]
// CTA 128 thr, tile 128 rows x 64 I-cols; 4 warps (2M x 2N), warp 64x32.
// Stage (u32), chunk c (stride 4096): A[0..2047] B1[2048..3071] B2[3072..4095]
// Inner loop software-pipelined: B frags of BOTH chunks preloaded;
// A regs reused across chunks (chunk-1 A loads hide under chunk-0 MMAs).
// =====================================================================
__global__ void __launch_bounds__(128, 2) pass1_mma() {
    extern __shared__ uint32_t sm[];
    const uint32_t sb = smem_u32(sm);
    const int tid = threadIdx.x, lane = tid & 31, warp = tid >> 5;
    const int m0 = blockIdx.y * 128;
    const int i0 = blockIdx.x * 64;
    const int e  = g_pair_expert[m0];

    const int tok = g_pair_token[m0 + tid];
    const uint32_t asz = (tok >= 0) ? 16u : 0u;
    const uint32_t* ap = g_hid + (size_t)(tok >= 0 ? tok : 0) * HROW;
    const int bcol = tid & 63, bgh = (tid >> 6) * 2;
    const uint32_t* b1p = g_w1 + ((size_t)e * I_DIM + i0 + bcol) * HROW;
    const uint32_t* b2p = g_w3 + ((size_t)e * I_DIM + i0 + bcol) * HROW;

    const int warp_m = warp >> 1, warp_n = warp & 1;
    const int rbase = warp_m * 64 + (lane >> 2);
    const int cbase = warp_n * 32 + (lane >> 2);
    const int t4    = (lane & 3) * 4;

    float accg[4][4][4], accu[4][4][4];
#pragma unroll
    for (int fm = 0; fm < 4; ++fm)
#pragma unroll
        for (int fn = 0; fn < 4; ++fn)
#pragma unroll
            for (int x = 0; x < 4; ++x) { accg[fm][fn][x] = 0.f; accu[fm][fn][x] = 0.f; }

    const int NK = H_DIM / KBLK;   // 64

#pragma unroll
    for (int s = 0; s < STAGES - 1; ++s) {
        uint32_t base = sb + s * STAGE_U32 * 4;
        int kc0 = s * 2;
#pragma unroll
        for (int c = 0; c < 2; ++c) {
            const uint32_t co = (kc0 + c) * 16;
#pragma unroll
            for (int g = 0; g < 4; ++g)
                cp16(base + (c*4096 + tid*16 + g*4) * 4, ap + co + g*4, asz);
#pragma unroll
            for (int j = 0; j < 2; ++j) {
                cp16(base + (c*4096 + 2048 + bcol*16 + (bgh+j)*4) * 4, b1p + co + (bgh+j)*4, 16);
                cp16(base + (c*4096 + 3072 + bcol*16 + (bgh+j)*4) * 4, b2p + co + (bgh+j)*4, 16);
            }
        }
        CP_COMMIT();
    }

#pragma unroll 1
    for (int i = 0; i < NK; ++i) {
        CP_WAIT1();
        __syncthreads();

        int ld = i + STAGES - 1;
        if (ld < NK) {
            uint32_t base = sb + (ld % STAGES) * STAGE_U32 * 4;
            int kc0 = ld * 2;
#pragma unroll
            for (int c = 0; c < 2; ++c) {
                const uint32_t co = (kc0 + c) * 16;
#pragma unroll
                for (int g = 0; g < 4; ++g)
                    cp16(base + (c*4096 + tid*16 + g*4) * 4, ap + co + g*4, asz);
#pragma unroll
                for (int j = 0; j < 2; ++j) {
                    cp16(base + (c*4096 + 2048 + bcol*16 + (bgh+j)*4) * 4, b1p + co + (bgh+j)*4, 16);
                    cp16(base + (c*4096 + 3072 + bcol*16 + (bgh+j)*4) * 4, b2p + co + (bgh+j)*4, 16);
                }
            }
        }
        CP_COMMIT();

        const uint32_t* stg = sm + (i % STAGES) * STAGE_U32;
        const uint32_t* st0 = stg;
        const uint32_t* st1 = stg + 4096;

        // --- preload B fragments for BOTH chunks + A for chunk 0 ---
        uint4 b1v0[4], b2v0[4], b1v1[4], b2v1[4];
#pragma unroll
        for (int fn = 0; fn < 4; ++fn) {
            int cc = (cbase + fn * 8) * 16 + t4;
            b1v0[fn] = *(const uint4*)(st0 + 2048 + cc);
            b2v0[fn] = *(const uint4*)(st0 + 3072 + cc);
            b1v1[fn] = *(const uint4*)(st1 + 2048 + cc);
            b2v1[fn] = *(const uint4*)(st1 + 3072 + cc);
        }
        uint4 av0[4], av8[4];
#pragma unroll
        for (int fm = 0; fm < 4; ++fm) {
            int rr = rbase + fm * 16;
            av0[fm] = *(const uint4*)(st0 + rr * 16 + t4);
            av8[fm] = *(const uint4*)(st0 + (rr + 8) * 16 + t4);
        }

        // --- chunk 0 MMAs ---
#pragma unroll
        for (int fm = 0; fm < 4; ++fm)
#pragma unroll
            for (int fn = 0; fn < 4; ++fn)
                mma_bf16(accg[fm][fn], av0[fm].x, av8[fm].x, av0[fm].y, av8[fm].y, b1v0[fn].x, b1v0[fn].y);
#pragma unroll
        for (int fm = 0; fm < 4; ++fm)
#pragma unroll
            for (int fn = 0; fn < 4; ++fn)
                mma_bf16(accu[fm][fn], av0[fm].x, av8[fm].x, av0[fm].y, av8[fm].y, b2v0[fn].x, b2v0[fn].y);
#pragma unroll
        for (int fm = 0; fm < 4; ++fm)
#pragma unroll
            for (int fn = 0; fn < 4; ++fn)
                mma_bf16(accg[fm][fn], av0[fm].x, av8[fm].x, av0[fm].y, av8[fm].y, b1v0[fn].z, b1v0[fn].w);
#pragma unroll
        for (int fm = 0; fm < 4; ++fm)
#pragma unroll
            for (int fn = 0; fn < 4; ++fn)
                mma_bf16(accu[fm][fn], av0[fm].x, av8[fm].x, av0[fm].y, av8[fm].y, b2v0[fn].z, b2v0[fn].w);
#pragma unroll
        for (int fm = 0; fm < 4; ++fm)
#pragma unroll
            for (int fn = 0; fn < 4; ++fn)
                mma_bf16(accg[fm][fn], av0[fm].z, av8[fm].z, av0[fm].w, av8[fm].w, b1v0[fn].x, b1v0[fn].y);
#pragma unroll
        for (int fm = 0; fm < 4; ++fm)
#pragma unroll
            for (int fn = 0; fn < 4; ++fn)
                mma_bf16(accu[fm][fn], av0[fm].z, av8[fm].z, av0[fm].w, av8[fm].w, b2v0[fn].x, b2v0[fn].y);

        // --- reload A (chunk 1) into the same registers (chunk-0 A is dead) ---
#pragma unroll
        for (int fm = 0; fm < 4; ++fm) {
            int rr = rbase + fm * 16;
            av0[fm] = *(const uint4*)(st1 + rr * 16 + t4);
            av8[fm] = *(const uint4*)(st1 + (rr + 8) * 16 + t4);
        }

        // --- chunk 1 MMAs ---
#pragma unroll
        for (int fm = 0; fm < 4; ++fm)
#pragma unroll
            for (int fn = 0; fn < 4; ++fn)
                mma_bf16(accg[fm][fn], av0[fm].x, av8[fm].x, av0[fm].y, av8[fm].y, b1v1[fn].x, b1v1[fn].y);
#pragma unroll
        for (int fm = 0; fm < 4; ++fm)
#pragma unroll
            for (int fn = 0; fn < 4; ++fn)
                mma_bf16(accu[fm][fn], av0[fm].x, av8[fm].x, av0[fm].y, av8[fm].y, b2v1[fn].x, b2v1[fn].y);
#pragma unroll
        for (int fm = 0; fm < 4; ++fm)
#pragma unroll
            for (int fn = 0; fn < 4; ++fn)
                mma_bf16(accg[fm][fn], av0[fm].x, av8[fm].x, av0[fm].y, av8[fm].y, b1v1[fn].z, b1v1[fn].w);
#pragma unroll
        for (int fm = 0; fm < 4; ++fm)
#pragma unroll
            for (int fn = 0; fn < 4; ++fn)
                mma_bf16(accu[fm][fn], av0[fm].x, av8[fm].x, av0[fm].y, av8[fm].y, b2v1[fn].z, b2v1[fn].w);
#pragma unroll
        for (int fm = 0; fm < 4; ++fm)
#pragma unroll
            for (int fn = 0; fn < 4; ++fn)
                mma_bf16(accg[fm][fn], av0[fm].z, av8[fm].z, av0[fm].w, av8[fm].w, b1v1[fn].x, b1v1[fn].y);
#pragma unroll
        for (int fm = 0; fm < 4; ++fm)
#pragma unroll
            for (int fn = 0; fn < 4; ++fn)
                mma_bf16(accu[fm][fn], av0[fm].z, av8[fm].z, av0[fm].w, av8[fm].w, b2v1[fn].x, b2v1[fn].y);
    }

    // ---- epilogue: silu*up*wt, split hi/lo, interleaved store ----
#pragma unroll
    for (int fm = 0; fm < 4; ++fm) {
        int r0 = m0 + rbase + fm * 16;
        int r1 = r0 + 8;
        float w0 = g_pair_w[r0];
        float w1_ = g_pair_w[r1];
#pragma unroll
        for (int fn = 0; fn < 4; ++fn) {
            int colg = i0 + warp_n * 32 + fn * 8 + (lane & 3) * 2;
            int chunk = colg >> 4;
            int kpin = (colg >> 1) & 7;
            int mm = 2 * (kpin & 3) + (kpin >> 2);
            size_t o0 = (size_t)r0 * IROW + chunk * 16 + (mm >> 1) * 4 + (mm & 1);
            size_t o1 = (size_t)r1 * IROW + chunk * 16 + (mm >> 1) * 4 + (mm & 1);
            float v0 = silu_mul(accg[fm][fn][0], accu[fm][fn][0], w0);
            float v1 = silu_mul(accg[fm][fn][1], accu[fm][fn][1], w0);
            float v2 = silu_mul(accg[fm][fn][2], accu[fm][fn][2], w1_);
            float v3 = silu_mul(accg[fm][fn][3], accu[fm][fn][3], w1_);
            __nv_bfloat16 h0 = __float2bfloat16(v0), h1 = __float2bfloat16(v1);
            __nv_bfloat16 h2 = __float2bfloat16(v2), h3 = __float2bfloat16(v3);
            g_act[o0]     = pack2(h0, h1);
            g_act[o0 + 2] = pack2(__float2bfloat16(v0 - __bfloat162float(h0)),
                                  __float2bfloat16(v1 - __bfloat162float(h1)));
            g_act[o1]     = pack2(h2, h3);
            g_act[o1 + 2] = pack2(__float2bfloat16(v2 - __bfloat162float(h2)),
                                  __float2bfloat16(v3 - __bfloat162float(h3)));
        }
    }
}

// =====================================================================
// pass 2: out[token] += act @ w2^T   [bf16x3, interleaved]
// CTA 128 thr, tile 128 rows x 128 H-cols; 4 warps (2M x 2N), warp 64x64.
// Software-pipelined: A frags of BOTH chunks preloaded; B regs reused.
// =====================================================================
__global__ void __launch_bounds__(128, 2) pass2_mma(float* __restrict__ out) {
    extern __shared__ uint32_t sm[];
    const uint32_t sb = smem_u32(sm);
    const int tid = threadIdx.x, lane = tid & 31, warp = tid >> 5;
    const int m0 = blockIdx.y * 128;
    const int h0 = blockIdx.x * 128;
    const int e  = g_pair_expert[m0];

    const uint32_t* ap = g_act + (size_t)(m0 + tid) * IROW;
    const uint32_t* bp = g_w2g + ((size_t)e * H_DIM + h0 + tid) * IROW;

    const int warp_m = warp >> 1, warp_n = warp & 1;
    const int rbase = warp_m * 64 + (lane >> 2);
    const int cbase = warp_n * 64 + (lane >> 2);
    const int t4    = (lane & 3) * 4;

    float acc[4][8][4];
#pragma unroll
    for (int fm = 0; fm < 4; ++fm)
#pragma unroll
        for (int fn = 0; fn < 8; ++fn)
#pragma unroll
            for (int x = 0; x < 4; ++x) acc[fm][fn][x] = 0.f;

    const int NK = I_DIM / KBLK;   // 176

#pragma unroll
    for (int s = 0; s < STAGES - 1; ++s) {
        uint32_t base = sb + s * STAGE_U32 * 4;
        int kc0 = s * 2;
#pragma unroll
        for (int c = 0; c < 2; ++c) {
            const uint32_t co = (kc0 + c) * 16;
#pragma unroll
            for (int g = 0; g < 4; ++g) {
                cp16(base + (c*4096 + tid*16 + g*4) * 4,        ap + co + g*4, 16);
                cp16(base + (c*4096 + 2048 + tid*16 + g*4) * 4, bp + co + g*4, 16);
            }
        }
        CP_COMMIT();
    }

#pragma unroll 1
    for (int i = 0; i < NK; ++i) {
        CP_WAIT1();
        __syncthreads();

        int ld = i + STAGES - 1;
        if (ld < NK) {
            uint32_t base = sb + (ld % STAGES) * STAGE_U32 * 4;
            int kc0 = ld * 2;
#pragma unroll
            for (int c = 0; c < 2; ++c) {
                const uint32_t co = (kc0 + c) * 16;
#pragma unroll
                for (int g = 0; g < 4; ++g) {
                    cp16(base + (c*4096 + tid*16 + g*4) * 4,        ap + co + g*4, 16);
                    cp16(base + (c*4096 + 2048 + tid*16 + g*4) * 4, bp + co + g*4, 16);
                }
            }
        }
        CP_COMMIT();

        const uint32_t* stg = sm + (i % STAGES) * STAGE_U32;
        const uint32_t* st0 = stg;
        const uint32_t* st1 = stg + 4096;

        // --- preload A fragments for BOTH chunks + B for chunk 0 ---
        uint4 a00[4], a80[4], a01[4], a81[4];
#pragma unroll
        for (int fm = 0; fm < 4; ++fm) {
            int rr = rbase + fm * 16;
            a00[fm] = *(const uint4*)(st0 + rr * 16 + t4);
            a80[fm] = *(const uint4*)(st0 + (rr + 8) * 16 + t4);
            a01[fm] = *(const uint4*)(st1 + rr * 16 + t4);
            a81[fm] = *(const uint4*)(st1 + (rr + 8) * 16 + t4);
        }
        uint4 bv[8];
#pragma unroll
        for (int fn = 0; fn < 8; ++fn)
            bv[fn] = *(const uint4*)(st0 + 2048 + (cbase + fn * 8) * 16 + t4);

        // --- chunk 0 MMAs ---
#pragma unroll
        for (int fm = 0; fm < 4; ++fm)
#pragma unroll
            for (int fn = 0; fn < 8; ++fn)
                mma_bf16(acc[fm][fn], a00[fm].x, a80[fm].x, a00[fm].y, a80[fm].y, bv[fn].x, bv[fn].y);
#pragma unroll
        for (int fm = 0; fm < 4; ++fm)
#pragma unroll
            for (int fn = 0; fn < 8; ++fn)
                mma_bf16(acc[fm][fn], a00[fm].x, a80[fm].x, a00[fm].y, a80[fm].y, bv[fn].z, bv[fn].w);
#pragma unroll
        for (int fm = 0; fm < 4; ++fm)
#pragma unroll
            for (int fn = 0; fn < 8; ++fn)
                mma_bf16(acc[fm][fn], a00[fm].z, a80[fm].z, a00[fm].w, a80[fm].w, bv[fn].x, bv[fn].y);

        // --- reload B for chunk 1 (chunk-0 B dead) ---
#pragma unroll
        for (int fn = 0; fn < 8; ++fn)
            bv[fn] = *(const uint4*)(st1 + 2048 + (cbase + fn * 8) * 16 + t4);

        // --- chunk 1 MMAs ---
#pragma unroll
        for (int fm = 0; fm < 4; ++fm)
#pragma unroll
            for (int fn = 0; fn < 8; ++fn)
                mma_bf16(acc[fm][fn], a01[fm].x, a81[fm].x, a01[fm].y, a81[fm].y, bv[fn].x, bv[fn].y);
#pragma unroll
        for (int fm = 0; fm < 4; ++fm)
#pragma unroll
            for (int fn = 0; fn < 8; ++fn)
                mma_bf16(acc[fm][fn], a01[fm].x, a81[fm].x, a01[fm].y, a81[fm].y, bv[fn].z, bv[fn].w);
#pragma unroll
        for (int fm = 0; fm < 4; ++fm)
#pragma unroll
            for (int fn = 0; fn < 8; ++fn)
                mma_bf16(acc[fm][fn], a01[fm].z, a81[fm].z, a01[fm].w, a81[fm].w, bv[fn].x, bv[fn].y);
    }

    // ---- epilogue: scatter-add ----
#pragma unroll
    for (int fm = 0; fm < 4; ++fm) {
        int r0 = m0 + rbase + fm * 16;
        int r1 = r0 + 8;
        int tok0 = g_pair_token[r0];
        int tok1 = g_pair_token[r1];
        float* o0 = (tok0 >= 0) ? out + (size_t)tok0 * H_DIM + h0 + warp_n * 64 + (lane & 3) * 2 : (float*)0;
        float* o1 = (tok1 >= 0) ? out + (size_t)tok1 * H_DIM + h0 + warp_n * 64 + (lane & 3) * 2 : (float*)0;
#pragma unroll
        for (int fn = 0; fn < 8; ++fn) {
            if (o0) {
                atomicAdd(o0 + fn * 8,     acc[fm][fn][0]);
                atomicAdd(o0 + fn * 8 + 1, acc[fm][fn][1]);
            }
            if (o1) {
                atomicAdd(o1 + fn * 8,     acc[fm][fn][2]);
                atomicAdd(o1 + fn * 8 + 1, acc[fm][fn][3]);
            }
        }
    }
}

// ---------------- launch ----------------
extern "C" void kernel_launch(void* const* d_in, const int* in_sizes, int n_in,
                              void* d_out, int out_size)
{
    const float* hidden = (const float*)d_in[0];
    const float* logits = (const float*)d_in[1];
    const float* w1     = (const float*)d_in[2];
    const float* w2     = (const float*)d_in[3];
    const float* w3     = (const float*)d_in[4];
    float* out = (float*)d_out;

    static bool init_done = false;
    if (!init_done) {
        cudaFuncSetAttribute(pass1_mma, cudaFuncAttributeMaxDynamicSharedMemorySize, SMEM_SZ);
        cudaFuncSetAttribute(pass2_mma, cudaFuncAttributeMaxDynamicSharedMemorySize, SMEM_SZ);
        init_done = true;
    }

    // launches 1-3
    conv_all<<<(T_TOK + 2 * NE * I_DIM) * 4, 256>>>(hidden, w1, w3);
    init_route<<<(PAIR_CAP + 255) / 256, 256>>>(logits);
    scan_fill<<<1, 1024>>>();

    // launch 4: pass1 (ncu profiles this)
    pass1_mma<<<dim3(I_DIM / 64, NTILES_M), 128, SMEM_SZ>>>();

    conv_w2<<<dim3(11, NE * H_DIM), 256>>>(w2);
    zero_out<<<(T_TOK * H_DIM / 4) / 256, 256>>>((float4*)out);

    pass2_mma<<<dim3(H_DIM / 128, NTILES_M), 128, SMEM_SZ>>>(out);
}